// round 12
// baseline (speedup 1.0000x reference)
#include <cuda_runtime.h>
#include <math.h>
#include <cstdint>

#define Bc   8
#define Lc   2048
#define Dc   300
#define Hc   150
#define HP   160
#define BLc  (Bc * Lc)

__device__ float g_Qh [BLc * HP];
__device__ float g_Ah [BLc * HP];
__device__ float g_P  [BLc * HP];
__device__ float g_QhT[(size_t)Bc * HP * Lc];
__device__ float g_Hm [BLc * HP];
__device__ float g_G  [(size_t)Bc * Lc * Lc];

// ---------------- helpers (plain sm_80+ PTX, valid on compute_103) ---------
__device__ __forceinline__ uint32_t su32(const void* p) {
    return (uint32_t)__cvta_generic_to_shared(p);
}
__device__ __forceinline__ uint32_t f2tf32(float v) {
    uint32_t u; asm("cvt.rna.tf32.f32 %0, %1;" : "=r"(u) : "f"(v)); return u;
}
__device__ __forceinline__ void split32(float v, uint32_t& hi, uint32_t& lo) {
    hi = f2tf32(v);
    lo = f2tf32(v - __uint_as_float(hi));
}
__device__ __forceinline__ void mma8(float* c,
    uint32_t a0, uint32_t a1, uint32_t a2, uint32_t a3, uint32_t b0, uint32_t b1)
{
    asm volatile("mma.sync.aligned.m16n8k8.row.col.f32.tf32.tf32.f32 "
        "{%0,%1,%2,%3}, {%4,%5,%6,%7}, {%8,%9}, {%0,%1,%2,%3};"
        : "+f"(c[0]), "+f"(c[1]), "+f"(c[2]), "+f"(c[3])
        : "r"(a0), "r"(a1), "r"(a2), "r"(a3), "r"(b0), "r"(b1));
}
__device__ __forceinline__ void cpa16(uint32_t s, const void* g) {
    asm volatile("cp.async.cg.shared.global [%0], [%1], 16;" :: "r"(s), "l"(g));
}

// ---------------------------------------------------------------------------
// tf32 mma.sync GEMM: C[m][n] = sum_k A[m][k]*B[n][k]  (both K-major)
// Warps fixed 4(m) x 4(n), 512 threads. Warp tile 32 x (NTW*8); CTA tile
// 128 x (32*NTW). smem rows padded to 36 floats (conflict-free fragment LDS).
// 3xTF32 split (B splits hoisted, computed once per k8). cp.async dbl-buffer.
// ---------------------------------------------------------------------------
template<int NTW>
__global__ void __launch_bounds__(512) tf32_gemm(
    const float* __restrict__ gA, const float* __restrict__ gB, float* __restrict__ gC,
    long lda, long ldb, long ldc, long bA, long bB, long bC, int nStages)
{
    extern __shared__ float smem[];
    const int NT  = 32 * NTW;          // CTA N tile
    const int WN  = 8 * NTW;           // warp N tile
    const int ASZ = 128 * 36;
    const int BSZ = NT * 36;

    const int tid  = threadIdx.x;
    const int lane = tid & 31, wid = tid >> 5;
    const int warpM = wid & 3, warpN = wid >> 2;
    const int r4 = lane >> 2, c4 = lane & 3;

    const float* A = gA + (size_t)blockIdx.z * bA + (size_t)blockIdx.y * 128 * lda;
    const float* B = gB + (size_t)blockIdx.z * bB + (size_t)blockIdx.x * NT * ldb;
    float*       C = gC + (size_t)blockIdx.z * bC + (size_t)blockIdx.y * 128 * ldc
                        + (size_t)blockIdx.x * NT;

    float acc[2][NTW][4];
    #pragma unroll
    for (int mt = 0; mt < 2; ++mt)
        #pragma unroll
        for (int nt = 0; nt < NTW; ++nt)
            #pragma unroll
            for (int i = 0; i < 4; ++i) acc[mt][nt][i] = 0.f;

    auto issue = [&](int s) {
        const float* Ak = A + s * 32;
        const float* Bk = B + s * 32;
        float* dA = smem + (s & 1) * (ASZ + BSZ);
        float* dB = dA + ASZ;
        #pragma unroll 2
        for (int i = tid; i < 128 * 8; i += 512) {
            int r = i >> 3, g = i & 7;
            cpa16(su32(dA + r * 36 + g * 4), Ak + (size_t)r * lda + g * 4);
        }
        #pragma unroll 2
        for (int i = tid; i < NT * 8; i += 512) {
            int r = i >> 3, g = i & 7;
            cpa16(su32(dB + r * 36 + g * 4), Bk + (size_t)r * ldb + g * 4);
        }
        asm volatile("cp.async.commit_group;" ::: "memory");
    };

    issue(0);

    #pragma unroll 1
    for (int s = 0; s < nStages; ++s) {
        if (s + 1 < nStages) {
            issue(s + 1);
            asm volatile("cp.async.wait_group 1;" ::: "memory");
        } else {
            asm volatile("cp.async.wait_group 0;" ::: "memory");
        }
        __syncthreads();
        const float* cA = smem + (s & 1) * (ASZ + BSZ);
        const float* cB = cA + ASZ;

        #pragma unroll
        for (int k8 = 0; k8 < 4; ++k8) {
            const int k0 = k8 * 8;
            // B fragments: load + split ONCE per k8 (shared across mt)
            uint32_t bH[NTW][2], bL[NTW][2];
            #pragma unroll
            for (int nt = 0; nt < NTW; ++nt) {
                int col = warpN * WN + nt * 8 + r4;
                split32(cB[col * 36 + k0 + c4],     bH[nt][0], bL[nt][0]);
                split32(cB[col * 36 + k0 + c4 + 4], bH[nt][1], bL[nt][1]);
            }
            #pragma unroll
            for (int mt = 0; mt < 2; ++mt) {
                int row = warpM * 32 + mt * 16 + r4;
                uint32_t aH[4], aL[4];
                split32(cA[row * 36 + k0 + c4],           aH[0], aL[0]);
                split32(cA[(row + 8) * 36 + k0 + c4],     aH[1], aL[1]);
                split32(cA[row * 36 + k0 + c4 + 4],       aH[2], aL[2]);
                split32(cA[(row + 8) * 36 + k0 + c4 + 4], aH[3], aL[3]);
                #pragma unroll
                for (int nt = 0; nt < NTW; ++nt) {
                    mma8(acc[mt][nt], aH[0], aH[1], aH[2], aH[3], bL[nt][0], bL[nt][1]);
                    mma8(acc[mt][nt], aL[0], aL[1], aL[2], aL[3], bH[nt][0], bH[nt][1]);
                    mma8(acc[mt][nt], aH[0], aH[1], aH[2], aH[3], bH[nt][0], bH[nt][1]);
                }
            }
        }
        __syncthreads();
    }

    #pragma unroll
    for (int mt = 0; mt < 2; ++mt) {
        int row = warpM * 32 + mt * 16 + r4;
        #pragma unroll
        for (int nt = 0; nt < NTW; ++nt) {
            int col = warpN * WN + nt * 8 + c4 * 2;
            *(float2*)(C + (size_t)row * ldc + col)       = make_float2(acc[mt][nt][0], acc[mt][nt][1]);
            *(float2*)(C + (size_t)(row + 8) * ldc + col) = make_float2(acc[mt][nt][2], acc[mt][nt][3]);
        }
    }
}

// ---------------- Kernel 1: gate (FFMA, writes HP-padded) ----------------
__global__ __launch_bounds__(256) void gate_kernel(
    const float* __restrict__ X, const float* __restrict__ Wi, const float* __restrict__ Wu,
    const float* __restrict__ bi, const float* __restrict__ bu, float* __restrict__ Y)
{
    __shared__ float Xs[64 * 17], Wis[16 * 160], Wus[16 * 160];
    const int tid = threadIdx.x, tx = tid & 15, ty = tid >> 4, rb = blockIdx.x * 64;
    float accI[4][10], accU[4][10];
    #pragma unroll
    for (int i = 0; i < 4; ++i)
        #pragma unroll
        for (int j = 0; j < 10; ++j) { accI[i][j] = 0.f; accU[i][j] = 0.f; }

    for (int kk = 0; kk < Dc; kk += 16) {
        #pragma unroll
        for (int r = 0; r < 4; ++r) {
            int idx = tid + 256 * r, m = idx >> 4, k = idx & 15;
            Xs[m * 17 + k] = (kk + k < Dc) ? X[(size_t)(rb + m) * Dc + kk + k] : 0.f;
        }
        #pragma unroll
        for (int r = 0; r < 10; ++r) {
            int idx = tid + 256 * r, k = idx / 160, c = idx - k * 160;
            bool ok = (c < Hc) && (kk + k < Dc);
            Wis[k * 160 + c] = ok ? Wi[(size_t)(kk + k) * Hc + c] : 0.f;
            Wus[k * 160 + c] = ok ? Wu[(size_t)(kk + k) * Hc + c] : 0.f;
        }
        __syncthreads();
        #pragma unroll
        for (int k = 0; k < 16; ++k) {
            float xv[4];
            #pragma unroll
            for (int i = 0; i < 4; ++i) xv[i] = Xs[(ty * 4 + i) * 17 + k];
            #pragma unroll
            for (int j = 0; j < 10; ++j) {
                float wi = Wis[k * 160 + tx + 16 * j], wu = Wus[k * 160 + tx + 16 * j];
                #pragma unroll
                for (int i = 0; i < 4; ++i) { accI[i][j] += xv[i] * wi; accU[i][j] += xv[i] * wu; }
            }
        }
        __syncthreads();
    }
    #pragma unroll
    for (int j = 0; j < 10; ++j) {
        int c = tx + 16 * j;
        float bI = (c < Hc) ? bi[c] : 0.f, bU = (c < Hc) ? bu[c] : 0.f;
        #pragma unroll
        for (int i = 0; i < 4; ++i) {
            int row = rb + ty * 4 + i;
            float v = 0.f;
            if (c < Hc) {
                float si = 1.f / (1.f + expf(-(accI[i][j] + bI)));
                v = si * tanhf(accU[i][j] + bU);
            }
            Y[(size_t)row * HP + c] = v;
        }
    }
}

// ---------------- Kernel 2: P = Qh@Wg + bg ----------------
__global__ __launch_bounds__(256) void proj_kernel(
    const float* __restrict__ Xin, const float* __restrict__ Wg,
    const float* __restrict__ bg, float* __restrict__ P)
{
    __shared__ float Xs[64 * 17], Ws[16 * 160];
    const int tid = threadIdx.x, tx = tid & 15, ty = tid >> 4, rb = blockIdx.x * 64;
    float acc[4][10];
    #pragma unroll
    for (int i = 0; i < 4; ++i)
        #pragma unroll
        for (int j = 0; j < 10; ++j) acc[i][j] = 0.f;

    for (int kk = 0; kk < Hc; kk += 16) {
        #pragma unroll
        for (int r = 0; r < 4; ++r) {
            int idx = tid + 256 * r, m = idx >> 4, k = idx & 15;
            Xs[m * 17 + k] = Xin[(size_t)(rb + m) * HP + kk + k];
        }
        #pragma unroll
        for (int r = 0; r < 10; ++r) {
            int idx = tid + 256 * r, k = idx / 160, c = idx - k * 160;
            bool ok = (c < Hc) && (kk + k < Hc);
            Ws[k * 160 + c] = ok ? Wg[(size_t)(kk + k) * Hc + c] : 0.f;
        }
        __syncthreads();
        #pragma unroll
        for (int k = 0; k < 16; ++k) {
            float xv[4];
            #pragma unroll
            for (int i = 0; i < 4; ++i) xv[i] = Xs[(ty * 4 + i) * 17 + k];
            #pragma unroll
            for (int j = 0; j < 10; ++j) {
                float w = Ws[k * 160 + tx + 16 * j];
                #pragma unroll
                for (int i = 0; i < 4; ++i) acc[i][j] += xv[i] * w;
            }
        }
        __syncthreads();
    }
    #pragma unroll
    for (int j = 0; j < 10; ++j) {
        int c = tx + 16 * j;
        float bv = (c < Hc) ? bg[c] : 0.f;
        #pragma unroll
        for (int i = 0; i < 4; ++i) {
            int row = rb + ty * 4 + i;
            P[(size_t)row * HP + c] = (c < Hc) ? (acc[i][j] + bv) : 0.f;
        }
    }
}

// ---------------- Kernel 2b: QhT[b][h][q] = Qh[b][q][h] ----------------
__global__ void transpose_kernel(const float* __restrict__ Qh, float* __restrict__ QhT)
{
    __shared__ float t[32][33];
    const int tx = threadIdx.x, ty = threadIdx.y;
    const int b = blockIdx.z, q0 = blockIdx.x * 32, h0 = blockIdx.y * 32;
    #pragma unroll
    for (int j = 0; j < 4; ++j)
        t[ty + 8 * j][tx] = Qh[((size_t)b * Lc + q0 + ty + 8 * j) * HP + h0 + tx];
    __syncthreads();
    #pragma unroll
    for (int j = 0; j < 4; ++j)
        QhT[((size_t)b * HP + h0 + ty + 8 * j) * Lc + q0 + tx] = t[tx][ty + 8 * j];
}

// ---------------- Kernel 4: row softmax over q ----------------
__global__ __launch_bounds__(256) void softmax_kernel(float* __restrict__ G)
{
    __shared__ float red[32];
    const size_t base = (size_t)blockIdx.x * Lc;
    const int tid = threadIdx.x;
    float v[8], m = -1e30f;
    #pragma unroll
    for (int r = 0; r < 8; ++r) { v[r] = G[base + tid + 256 * r]; m = fmaxf(m, v[r]); }
    #pragma unroll
    for (int o = 16; o > 0; o >>= 1) m = fmaxf(m, __shfl_xor_sync(0xffffffffu, m, o));
    if ((tid & 31) == 0) red[tid >> 5] = m;
    __syncthreads();
    if (tid < 32) {
        float t = (tid < 8) ? red[tid] : -1e30f;
        #pragma unroll
        for (int o = 4; o > 0; o >>= 1) t = fmaxf(t, __shfl_xor_sync(0xffffffffu, t, o));
        if (tid == 0) red[0] = t;
    }
    __syncthreads();
    m = red[0];
    float s = 0.f;
    #pragma unroll
    for (int r = 0; r < 8; ++r) { v[r] = __expf(v[r] - m); s += v[r]; }
    #pragma unroll
    for (int o = 16; o > 0; o >>= 1) s += __shfl_xor_sync(0xffffffffu, s, o);
    __syncthreads();
    if ((tid & 31) == 0) red[tid >> 5] = s;
    __syncthreads();
    if (tid < 32) {
        float t = (tid < 8) ? red[tid] : 0.f;
        #pragma unroll
        for (int o = 4; o > 0; o >>= 1) t += __shfl_xor_sync(0xffffffffu, t, o);
        if (tid == 0) red[0] = t;
    }
    __syncthreads();
    const float inv = 1.f / red[0];
    #pragma unroll
    for (int r = 0; r < 8; ++r) G[base + tid + 256 * r] = v[r] * inv;
}

// ---------------- Kernel 6: T = relu([Ah,Hm]@Wt + bt) ----------------
__global__ __launch_bounds__(256) void out_kernel(
    const float* __restrict__ Ah, const float* __restrict__ Hm,
    const float* __restrict__ Wt, const float* __restrict__ bt, float* __restrict__ T)
{
    __shared__ float Xs[64 * 17], Ws[16 * 160];
    const int tid = threadIdx.x, tx = tid & 15, ty = tid >> 4, rb = blockIdx.x * 64;
    float acc[4][10];
    #pragma unroll
    for (int i = 0; i < 4; ++i)
        #pragma unroll
        for (int j = 0; j < 10; ++j) acc[i][j] = 0.f;

    for (int ph = 0; ph < 2; ++ph) {
        const float* X = ph ? Hm : Ah;
        const int wofs = ph ? Hc : 0;
        for (int kk = 0; kk < Hc; kk += 16) {
            #pragma unroll
            for (int r = 0; r < 4; ++r) {
                int idx = tid + 256 * r, m = idx >> 4, k = idx & 15;
                Xs[m * 17 + k] = X[(size_t)(rb + m) * HP + kk + k];
            }
            #pragma unroll
            for (int r = 0; r < 10; ++r) {
                int idx = tid + 256 * r, k = idx / 160, c = idx - k * 160;
                bool ok = (c < Hc) && (kk + k < Hc);
                Ws[k * 160 + c] = ok ? Wt[(size_t)(wofs + kk + k) * Hc + c] : 0.f;
            }
            __syncthreads();
            #pragma unroll
            for (int k = 0; k < 16; ++k) {
                float xv[4];
                #pragma unroll
                for (int i = 0; i < 4; ++i) xv[i] = Xs[(ty * 4 + i) * 17 + k];
                #pragma unroll
                for (int j = 0; j < 10; ++j) {
                    float w = Ws[k * 160 + tx + 16 * j];
                    #pragma unroll
                    for (int i = 0; i < 4; ++i) acc[i][j] += xv[i] * w;
                }
            }
            __syncthreads();
        }
    }
    #pragma unroll
    for (int j = 0; j < 10; ++j) {
        int c = tx + 16 * j;
        if (c < Hc) {
            float bv = bt[c];
            #pragma unroll
            for (int i = 0; i < 4; ++i) {
                int row = rb + ty * 4 + i;
                T[(size_t)row * Hc + c] = fmaxf(acc[i][j] + bv, 0.f);
            }
        }
    }
}

// ---------------- Launch ----------------
extern "C" void kernel_launch(void* const* d_in, const int* in_sizes, int n_in,
                              void* d_out, int out_size)
{
    const float* Q  = (const float*)d_in[0];
    const float* A  = (const float*)d_in[1];
    const float* Wi = (const float*)d_in[2];
    const float* Wu = (const float*)d_in[3];
    const float* Wg = (const float*)d_in[4];
    const float* Wt = (const float*)d_in[5];
    const float* bi = (const float*)d_in[6];
    const float* bu = (const float*)d_in[7];
    const float* bg = (const float*)d_in[8];
    const float* bt = (const float*)d_in[9];
    float* out = (float*)d_out;

    float *Qh, *Ah, *P, *QhT, *G, *Hm;
    cudaGetSymbolAddress((void**)&Qh,  g_Qh);
    cudaGetSymbolAddress((void**)&Ah,  g_Ah);
    cudaGetSymbolAddress((void**)&P,   g_P);
    cudaGetSymbolAddress((void**)&QhT, g_QhT);
    cudaGetSymbolAddress((void**)&G,   g_G);
    cudaGetSymbolAddress((void**)&Hm,  g_Hm);

    const int smem_score = 2 * (128 * 36 + 128 * 36) * 4;   // 73728 B
    const int smem_hm    = 2 * (128 * 36 + 160 * 36) * 4;   // 82944 B
    cudaFuncSetAttribute(tf32_gemm<4>, cudaFuncAttributeMaxDynamicSharedMemorySize, smem_score);
    cudaFuncSetAttribute(tf32_gemm<5>, cudaFuncAttributeMaxDynamicSharedMemorySize, smem_hm);

    gate_kernel<<<BLc / 64, 256>>>(Q, Wi, Wu, bi, bu, Qh);
    gate_kernel<<<BLc / 64, 256>>>(A, Wi, Wu, bi, bu, Ah);
    proj_kernel<<<BLc / 64, 256>>>(Qh, Wg, bg, P);

    dim3 tg(Lc / 32, HP / 32, Bc);
    transpose_kernel<<<tg, dim3(32, 8)>>>(Qh, QhT);

    // scores: C=G[b][a][q], A=Ah (m=a, k=h), B=P (n=q, k=h), K=160 -> 5 stages
    tf32_gemm<4><<<dim3(16, 16, 8), 512, smem_score>>>(
        Ah, P, G, HP, HP, Lc,
        (long)Lc * HP, (long)Lc * HP, (long)Lc * Lc, 5);

    softmax_kernel<<<Bc * Lc, 256>>>(G);

    // Hm: C=Hm[b][a][h], A=G (m=a, k=q), B=QhT (n=h, k=q), K=2048 -> 64 stages
    tf32_gemm<5><<<dim3(1, 16, 8), 512, smem_hm>>>(
        G, QhT, Hm, Lc, Lc, HP,
        (long)Lc * Lc, (long)HP * Lc, (long)Lc * HP, 64);

    out_kernel<<<BLc / 64, 256>>>(Ah, Hm, Wt, bt, out);
}

// round 13
// speedup vs baseline: 1.0631x; 1.0631x over previous
#include <cuda_runtime.h>
#include <math.h>
#include <cstdint>

#define Bc   8
#define Lc   2048
#define Dc   300
#define Hc   150
#define HP   160
#define BLc  (Bc * Lc)

__device__ float g_Qh [BLc * HP];
__device__ float g_Ah [BLc * HP];
__device__ float g_P  [BLc * HP];
__device__ float g_QhT[(size_t)Bc * HP * Lc];
__device__ float g_Hm [BLc * HP];

// ---------------- helpers (plain sm_80+ PTX, valid on compute_103) ---------
__device__ __forceinline__ uint32_t su32(const void* p) {
    return (uint32_t)__cvta_generic_to_shared(p);
}
__device__ __forceinline__ uint32_t f2tf32(float v) {
    uint32_t u; asm("cvt.rna.tf32.f32 %0, %1;" : "=r"(u) : "f"(v)); return u;
}
__device__ __forceinline__ void split32(float v, uint32_t& hi, uint32_t& lo) {
    hi = f2tf32(v);
    lo = f2tf32(v - __uint_as_float(hi));
}
__device__ __forceinline__ void mma8(float* c,
    uint32_t a0, uint32_t a1, uint32_t a2, uint32_t a3, uint32_t b0, uint32_t b1)
{
    asm volatile("mma.sync.aligned.m16n8k8.row.col.f32.tf32.tf32.f32 "
        "{%0,%1,%2,%3}, {%4,%5,%6,%7}, {%8,%9}, {%0,%1,%2,%3};"
        : "+f"(c[0]), "+f"(c[1]), "+f"(c[2]), "+f"(c[3])
        : "r"(a0), "r"(a1), "r"(a2), "r"(a3), "r"(b0), "r"(b1));
}
__device__ __forceinline__ void cpa16(uint32_t s, const void* g) {
    asm volatile("cp.async.cg.shared.global [%0], [%1], 16;" :: "r"(s), "l"(g));
}
#define CP_COMMIT  asm volatile("cp.async.commit_group;" ::: "memory")
#define CP_WAIT1   asm volatile("cp.async.wait_group 1;" ::: "memory")
#define CP_WAIT0   asm volatile("cp.async.wait_group 0;" ::: "memory")

// ---------------------------------------------------------------------------
// Fused flash attention: for each (b, a-tile of 128):
//   S = Ah_tile @ P^T (over h=160), online softmax over q, O += Pexp @ Qh
//   Hm = O / l      (3xTF32 mma.sync throughout; no G materialization)
// Warps 4(m=a) x 4(n).  S-GEMM warp n-tile 32 (q); O-GEMM warp n-tile 40 (h).
// smem (floats): Ah 128x164 | R1: P-stages(2x128x36) U Pexp(128x132) |
//                R2: V-stages 2x160x36 | red 4x128 | m,l,f 3x128
// ---------------------------------------------------------------------------
#define OFF_R1  20992
#define OFF_R2  37888
#define OFF_RED 49408
#define OFF_M   49920
#define OFF_L   50048
#define OFF_F   50176
#define SM_ATTN (50304 * 4)

__global__ void __launch_bounds__(512) attn_tc(
    const float* __restrict__ Ah, const float* __restrict__ P,
    const float* __restrict__ QhT, float* __restrict__ Hm)
{
    extern __shared__ float sm[];
    float* AhS = sm;
    float* red = sm + OFF_RED;
    float* mS  = sm + OFF_M;
    float* lS  = sm + OFF_L;
    float* fS  = sm + OFF_F;

    const int tid = threadIdx.x, lane = tid & 31, wid = tid >> 5;
    const int warpM = wid & 3, warpN = wid >> 2;
    const int r4 = lane >> 2, c4 = lane & 3;
    const int b = blockIdx.y, aBase = blockIdx.x * 128;

    const float* Ab = Ah  + ((size_t)b * Lc + aBase) * HP;
    const float* Pb = P   + (size_t)b * Lc * HP;
    const float* Vb = QhT + (size_t)b * HP * Lc;

    // resident Ah tile [128][164]
    for (int i = tid; i < 128 * 40; i += 512) {
        int r = i / 40, c = (i - r * 40) * 4;
        cpa16(su32(AhS + r * 164 + c), Ab + (size_t)r * HP + c);
    }
    CP_COMMIT; CP_WAIT0;
    if (tid < 128) { mS[tid] = -1e30f; lS[tid] = 0.f; }
    __syncthreads();

    float accO[2][5][4];
    #pragma unroll
    for (int mt = 0; mt < 2; ++mt)
        #pragma unroll
        for (int nt = 0; nt < 5; ++nt)
            #pragma unroll
            for (int i = 0; i < 4; ++i) accO[mt][nt][i] = 0.f;

    const int row0b = warpM * 32 + r4;   // + mt*16 (+8)

    #pragma unroll 1
    for (int qt = 0; qt < 16; ++qt) {
        const int q0 = qt * 128;
        float accS[2][4][4];
        #pragma unroll
        for (int mt = 0; mt < 2; ++mt)
            #pragma unroll
            for (int nt = 0; nt < 4; ++nt)
                #pragma unroll
                for (int i = 0; i < 4; ++i) accS[mt][nt][i] = 0.f;

        // ---- S-GEMM over h (5 stages of 32) ----
        auto issueP = [&](int s) {
            float* d = sm + OFF_R1 + (s & 1) * (128 * 36);
            #pragma unroll 2
            for (int i = tid; i < 128 * 8; i += 512) {
                int r = i >> 3, g = i & 7;
                cpa16(su32(d + r * 36 + g * 4), Pb + (size_t)(q0 + r) * HP + s * 32 + g * 4);
            }
            CP_COMMIT;
        };
        issueP(0);
        #pragma unroll 1
        for (int s = 0; s < 5; ++s) {
            if (s + 1 < 5) { issueP(s + 1); CP_WAIT1; } else { CP_WAIT0; }
            __syncthreads();
            const float* cB = sm + OFF_R1 + (s & 1) * (128 * 36);
            const int sk = s * 32;
            #pragma unroll
            for (int k8 = 0; k8 < 4; ++k8) {
                const int k0 = k8 * 8;
                uint32_t bH[4][2], bL[4][2];
                #pragma unroll
                for (int nt = 0; nt < 4; ++nt) {
                    int col = warpN * 32 + nt * 8 + r4;
                    split32(cB[col * 36 + k0 + c4],     bH[nt][0], bL[nt][0]);
                    split32(cB[col * 36 + k0 + c4 + 4], bH[nt][1], bL[nt][1]);
                }
                #pragma unroll
                for (int mt = 0; mt < 2; ++mt) {
                    int row = row0b + mt * 16;
                    uint32_t aH[4], aL[4];
                    split32(AhS[row * 164 + sk + k0 + c4],           aH[0], aL[0]);
                    split32(AhS[(row + 8) * 164 + sk + k0 + c4],     aH[1], aL[1]);
                    split32(AhS[row * 164 + sk + k0 + c4 + 4],       aH[2], aL[2]);
                    split32(AhS[(row + 8) * 164 + sk + k0 + c4 + 4], aH[3], aL[3]);
                    #pragma unroll
                    for (int nt = 0; nt < 4; ++nt) {
                        mma8(accS[mt][nt], aH[0], aH[1], aH[2], aH[3], bL[nt][0], bL[nt][1]);
                        mma8(accS[mt][nt], aL[0], aL[1], aL[2], aL[3], bH[nt][0], bH[nt][1]);
                        mma8(accS[mt][nt], aH[0], aH[1], aH[2], aH[3], bH[nt][0], bH[nt][1]);
                    }
                }
            }
            __syncthreads();
        }

        // ---- prefetch first V stage (overlaps softmax math) ----
        auto issueV = [&](int s) {
            float* d = sm + OFF_R2 + (s & 1) * (160 * 36);
            #pragma unroll 3
            for (int i = tid; i < 160 * 8; i += 512) {
                int r = i >> 3, g = i & 7;
                cpa16(su32(d + r * 36 + g * 4), Vb + (size_t)r * Lc + q0 + s * 32 + g * 4);
            }
            CP_COMMIT;
        };
        issueV(0);

        // ---- online softmax: tile row max ----
        #pragma unroll
        for (int mt = 0; mt < 2; ++mt) {
            int row = row0b + mt * 16;
            float m0 = -1e30f, m1 = -1e30f;
            #pragma unroll
            for (int nt = 0; nt < 4; ++nt) {
                m0 = fmaxf(m0, fmaxf(accS[mt][nt][0], accS[mt][nt][1]));
                m1 = fmaxf(m1, fmaxf(accS[mt][nt][2], accS[mt][nt][3]));
            }
            m0 = fmaxf(m0, __shfl_xor_sync(0xffffffffu, m0, 1));
            m0 = fmaxf(m0, __shfl_xor_sync(0xffffffffu, m0, 2));
            m1 = fmaxf(m1, __shfl_xor_sync(0xffffffffu, m1, 1));
            m1 = fmaxf(m1, __shfl_xor_sync(0xffffffffu, m1, 2));
            if (c4 == 0) {
                red[warpN * 128 + row]     = m0;
                red[warpN * 128 + row + 8] = m1;
            }
        }
        __syncthreads();
        if (warpN == 0 && c4 == 0) {
            #pragma unroll
            for (int mt = 0; mt < 2; ++mt)
                #pragma unroll
                for (int p = 0; p < 2; ++p) {
                    int row = row0b + mt * 16 + p * 8;
                    float t = fmaxf(fmaxf(red[row], red[128 + row]),
                                    fmaxf(red[256 + row], red[384 + row]));
                    float mo = mS[row], mn = fmaxf(mo, t);
                    fS[row] = __expf(mo - mn);
                    mS[row] = mn;
                }
        }
        __syncthreads();

        // ---- Pexp -> smem + row sums ----
        float* PE = sm + OFF_R1;   // [128][132]
        #pragma unroll
        for (int mt = 0; mt < 2; ++mt) {
            int row = row0b + mt * 16;
            float m0 = mS[row], m1 = mS[row + 8];
            float s0 = 0.f, s1 = 0.f;
            #pragma unroll
            for (int nt = 0; nt < 4; ++nt) {
                float e0 = __expf(accS[mt][nt][0] - m0);
                float e1 = __expf(accS[mt][nt][1] - m0);
                float e2 = __expf(accS[mt][nt][2] - m1);
                float e3 = __expf(accS[mt][nt][3] - m1);
                int col = warpN * 32 + nt * 8 + c4 * 2;
                *(float2*)(PE + row * 132 + col)       = make_float2(e0, e1);
                *(float2*)(PE + (row + 8) * 132 + col) = make_float2(e2, e3);
                s0 += e0 + e1; s1 += e2 + e3;
            }
            s0 += __shfl_xor_sync(0xffffffffu, s0, 1);
            s0 += __shfl_xor_sync(0xffffffffu, s0, 2);
            s1 += __shfl_xor_sync(0xffffffffu, s1, 1);
            s1 += __shfl_xor_sync(0xffffffffu, s1, 2);
            if (c4 == 0) {
                red[warpN * 128 + row]     = s0;
                red[warpN * 128 + row + 8] = s1;
            }
        }
        __syncthreads();
        if (warpN == 0 && c4 == 0) {
            #pragma unroll
            for (int mt = 0; mt < 2; ++mt)
                #pragma unroll
                for (int p = 0; p < 2; ++p) {
                    int row = row0b + mt * 16 + p * 8;
                    float ts = red[row] + red[128 + row] + red[256 + row] + red[384 + row];
                    lS[row] = lS[row] * fS[row] + ts;
                }
        }
        // ---- rescale O by factor ----
        #pragma unroll
        for (int mt = 0; mt < 2; ++mt) {
            int row = row0b + mt * 16;
            float f0 = fS[row], f1 = fS[row + 8];
            #pragma unroll
            for (int nt = 0; nt < 5; ++nt) {
                accO[mt][nt][0] *= f0; accO[mt][nt][1] *= f0;
                accO[mt][nt][2] *= f1; accO[mt][nt][3] *= f1;
            }
        }

        // ---- O-GEMM over q (4 stages of 32): O += PE @ V ----
        #pragma unroll 1
        for (int s = 0; s < 4; ++s) {
            if (s + 1 < 4) { issueV(s + 1); CP_WAIT1; } else { CP_WAIT0; }
            __syncthreads();
            const float* cB = sm + OFF_R2 + (s & 1) * (160 * 36);
            const int sq = s * 32;
            #pragma unroll
            for (int k8 = 0; k8 < 4; ++k8) {
                const int k0 = k8 * 8;
                uint32_t bH[5][2], bL[5][2];
                #pragma unroll
                for (int nt = 0; nt < 5; ++nt) {
                    int col = warpN * 40 + nt * 8 + r4;
                    split32(cB[col * 36 + k0 + c4],     bH[nt][0], bL[nt][0]);
                    split32(cB[col * 36 + k0 + c4 + 4], bH[nt][1], bL[nt][1]);
                }
                #pragma unroll
                for (int mt = 0; mt < 2; ++mt) {
                    int row = row0b + mt * 16;
                    uint32_t aH[4], aL[4];
                    split32(PE[row * 132 + sq + k0 + c4],           aH[0], aL[0]);
                    split32(PE[(row + 8) * 132 + sq + k0 + c4],     aH[1], aL[1]);
                    split32(PE[row * 132 + sq + k0 + c4 + 4],       aH[2], aL[2]);
                    split32(PE[(row + 8) * 132 + sq + k0 + c4 + 4], aH[3], aL[3]);
                    #pragma unroll
                    for (int nt = 0; nt < 5; ++nt) {
                        mma8(accO[mt][nt], aH[0], aH[1], aH[2], aH[3], bL[nt][0], bL[nt][1]);
                        mma8(accO[mt][nt], aL[0], aL[1], aL[2], aL[3], bH[nt][0], bH[nt][1]);
                        mma8(accO[mt][nt], aH[0], aH[1], aH[2], aH[3], bH[nt][0], bH[nt][1]);
                    }
                }
            }
            __syncthreads();
        }
    }

    // ---- final: Hm = O / l ----
    #pragma unroll
    for (int mt = 0; mt < 2; ++mt) {
        int row = row0b + mt * 16;
        float i0 = 1.f / lS[row], i1 = 1.f / lS[row + 8];
        #pragma unroll
        for (int nt = 0; nt < 5; ++nt) {
            int col = warpN * 40 + nt * 8 + c4 * 2;
            size_t o0 = ((size_t)b * Lc + aBase + row) * HP + col;
            size_t o1 = ((size_t)b * Lc + aBase + row + 8) * HP + col;
            *(float2*)(Hm + o0) = make_float2(accO[mt][nt][0] * i0, accO[mt][nt][1] * i0);
            *(float2*)(Hm + o1) = make_float2(accO[mt][nt][2] * i1, accO[mt][nt][3] * i1);
        }
    }
}

// ---------------- Kernel 1: gate (FFMA, writes HP-padded) ----------------
__global__ __launch_bounds__(256) void gate_kernel(
    const float* __restrict__ X, const float* __restrict__ Wi, const float* __restrict__ Wu,
    const float* __restrict__ bi, const float* __restrict__ bu, float* __restrict__ Y)
{
    __shared__ float Xs[64 * 17], Wis[16 * 160], Wus[16 * 160];
    const int tid = threadIdx.x, tx = tid & 15, ty = tid >> 4, rb = blockIdx.x * 64;
    float accI[4][10], accU[4][10];
    #pragma unroll
    for (int i = 0; i < 4; ++i)
        #pragma unroll
        for (int j = 0; j < 10; ++j) { accI[i][j] = 0.f; accU[i][j] = 0.f; }

    for (int kk = 0; kk < Dc; kk += 16) {
        #pragma unroll
        for (int r = 0; r < 4; ++r) {
            int idx = tid + 256 * r, m = idx >> 4, k = idx & 15;
            Xs[m * 17 + k] = (kk + k < Dc) ? X[(size_t)(rb + m) * Dc + kk + k] : 0.f;
        }
        #pragma unroll
        for (int r = 0; r < 10; ++r) {
            int idx = tid + 256 * r, k = idx / 160, c = idx - k * 160;
            bool ok = (c < Hc) && (kk + k < Dc);
            Wis[k * 160 + c] = ok ? Wi[(size_t)(kk + k) * Hc + c] : 0.f;
            Wus[k * 160 + c] = ok ? Wu[(size_t)(kk + k) * Hc + c] : 0.f;
        }
        __syncthreads();
        #pragma unroll
        for (int k = 0; k < 16; ++k) {
            float xv[4];
            #pragma unroll
            for (int i = 0; i < 4; ++i) xv[i] = Xs[(ty * 4 + i) * 17 + k];
            #pragma unroll
            for (int j = 0; j < 10; ++j) {
                float wi = Wis[k * 160 + tx + 16 * j], wu = Wus[k * 160 + tx + 16 * j];
                #pragma unroll
                for (int i = 0; i < 4; ++i) { accI[i][j] += xv[i] * wi; accU[i][j] += xv[i] * wu; }
            }
        }
        __syncthreads();
    }
    #pragma unroll
    for (int j = 0; j < 10; ++j) {
        int c = tx + 16 * j;
        float bI = (c < Hc) ? bi[c] : 0.f, bU = (c < Hc) ? bu[c] : 0.f;
        #pragma unroll
        for (int i = 0; i < 4; ++i) {
            int row = rb + ty * 4 + i;
            float v = 0.f;
            if (c < Hc) {
                float si = 1.f / (1.f + expf(-(accI[i][j] + bI)));
                v = si * tanhf(accU[i][j] + bU);
            }
            Y[(size_t)row * HP + c] = v;
        }
    }
}

// ---------------- Kernel 2: P = Qh@Wg + bg ----------------
__global__ __launch_bounds__(256) void proj_kernel(
    const float* __restrict__ Xin, const float* __restrict__ Wg,
    const float* __restrict__ bg, float* __restrict__ P)
{
    __shared__ float Xs[64 * 17], Ws[16 * 160];
    const int tid = threadIdx.x, tx = tid & 15, ty = tid >> 4, rb = blockIdx.x * 64;
    float acc[4][10];
    #pragma unroll
    for (int i = 0; i < 4; ++i)
        #pragma unroll
        for (int j = 0; j < 10; ++j) acc[i][j] = 0.f;

    for (int kk = 0; kk < Hc; kk += 16) {
        #pragma unroll
        for (int r = 0; r < 4; ++r) {
            int idx = tid + 256 * r, m = idx >> 4, k = idx & 15;
            Xs[m * 17 + k] = Xin[(size_t)(rb + m) * HP + kk + k];
        }
        #pragma unroll
        for (int r = 0; r < 10; ++r) {
            int idx = tid + 256 * r, k = idx / 160, c = idx - k * 160;
            bool ok = (c < Hc) && (kk + k < Hc);
            Ws[k * 160 + c] = ok ? Wg[(size_t)(kk + k) * Hc + c] : 0.f;
        }
        __syncthreads();
        #pragma unroll
        for (int k = 0; k < 16; ++k) {
            float xv[4];
            #pragma unroll
            for (int i = 0; i < 4; ++i) xv[i] = Xs[(ty * 4 + i) * 17 + k];
            #pragma unroll
            for (int j = 0; j < 10; ++j) {
                float w = Ws[k * 160 + tx + 16 * j];
                #pragma unroll
                for (int i = 0; i < 4; ++i) acc[i][j] += xv[i] * w;
            }
        }
        __syncthreads();
    }
    #pragma unroll
    for (int j = 0; j < 10; ++j) {
        int c = tx + 16 * j;
        float bv = (c < Hc) ? bg[c] : 0.f;
        #pragma unroll
        for (int i = 0; i < 4; ++i) {
            int row = rb + ty * 4 + i;
            P[(size_t)row * HP + c] = (c < Hc) ? (acc[i][j] + bv) : 0.f;
        }
    }
}

// ---------------- Kernel 2b: QhT[b][h][q] = Qh[b][q][h] ----------------
__global__ void transpose_kernel(const float* __restrict__ Qh, float* __restrict__ QhT)
{
    __shared__ float t[32][33];
    const int tx = threadIdx.x, ty = threadIdx.y;
    const int b = blockIdx.z, q0 = blockIdx.x * 32, h0 = blockIdx.y * 32;
    #pragma unroll
    for (int j = 0; j < 4; ++j)
        t[ty + 8 * j][tx] = Qh[((size_t)b * Lc + q0 + ty + 8 * j) * HP + h0 + tx];
    __syncthreads();
    #pragma unroll
    for (int j = 0; j < 4; ++j)
        QhT[((size_t)b * HP + h0 + ty + 8 * j) * Lc + q0 + tx] = t[tx][ty + 8 * j];
}

// ---------------- Kernel 6: T = relu([Ah,Hm]@Wt + bt) ----------------
__global__ __launch_bounds__(256) void out_kernel(
    const float* __restrict__ Ah, const float* __restrict__ Hm,
    const float* __restrict__ Wt, const float* __restrict__ bt, float* __restrict__ T)
{
    __shared__ float Xs[64 * 17], Ws[16 * 160];
    const int tid = threadIdx.x, tx = tid & 15, ty = tid >> 4, rb = blockIdx.x * 64;
    float acc[4][10];
    #pragma unroll
    for (int i = 0; i < 4; ++i)
        #pragma unroll
        for (int j = 0; j < 10; ++j) acc[i][j] = 0.f;

    for (int ph = 0; ph < 2; ++ph) {
        const float* X = ph ? Hm : Ah;
        const int wofs = ph ? Hc : 0;
        for (int kk = 0; kk < Hc; kk += 16) {
            #pragma unroll
            for (int r = 0; r < 4; ++r) {
                int idx = tid + 256 * r, m = idx >> 4, k = idx & 15;
                Xs[m * 17 + k] = X[(size_t)(rb + m) * HP + kk + k];
            }
            #pragma unroll
            for (int r = 0; r < 10; ++r) {
                int idx = tid + 256 * r, k = idx / 160, c = idx - k * 160;
                bool ok = (c < Hc) && (kk + k < Hc);
                Ws[k * 160 + c] = ok ? Wt[(size_t)(wofs + kk + k) * Hc + c] : 0.f;
            }
            __syncthreads();
            #pragma unroll
            for (int k = 0; k < 16; ++k) {
                float xv[4];
                #pragma unroll
                for (int i = 0; i < 4; ++i) xv[i] = Xs[(ty * 4 + i) * 17 + k];
                #pragma unroll
                for (int j = 0; j < 10; ++j) {
                    float w = Ws[k * 160 + tx + 16 * j];
                    #pragma unroll
                    for (int i = 0; i < 4; ++i) acc[i][j] += xv[i] * w;
                }
            }
            __syncthreads();
        }
    }
    #pragma unroll
    for (int j = 0; j < 10; ++j) {
        int c = tx + 16 * j;
        if (c < Hc) {
            float bv = bt[c];
            #pragma unroll
            for (int i = 0; i < 4; ++i) {
                int row = rb + ty * 4 + i;
                T[(size_t)row * Hc + c] = fmaxf(acc[i][j] + bv, 0.f);
            }
        }
    }
}

// ---------------- Launch ----------------
extern "C" void kernel_launch(void* const* d_in, const int* in_sizes, int n_in,
                              void* d_out, int out_size)
{
    const float* Q  = (const float*)d_in[0];
    const float* A  = (const float*)d_in[1];
    const float* Wi = (const float*)d_in[2];
    const float* Wu = (const float*)d_in[3];
    const float* Wg = (const float*)d_in[4];
    const float* Wt = (const float*)d_in[5];
    const float* bi = (const float*)d_in[6];
    const float* bu = (const float*)d_in[7];
    const float* bg = (const float*)d_in[8];
    const float* bt = (const float*)d_in[9];
    float* out = (float*)d_out;

    float *Qh, *Ah, *P, *QhT, *Hm;
    cudaGetSymbolAddress((void**)&Qh,  g_Qh);
    cudaGetSymbolAddress((void**)&Ah,  g_Ah);
    cudaGetSymbolAddress((void**)&P,   g_P);
    cudaGetSymbolAddress((void**)&QhT, g_QhT);
    cudaGetSymbolAddress((void**)&Hm,  g_Hm);

    cudaFuncSetAttribute(attn_tc, cudaFuncAttributeMaxDynamicSharedMemorySize, SM_ATTN);

    gate_kernel<<<BLc / 64, 256>>>(Q, Wi, Wu, bi, bu, Qh);
    gate_kernel<<<BLc / 64, 256>>>(A, Wi, Wu, bi, bu, Ah);
    proj_kernel<<<BLc / 64, 256>>>(Qh, Wg, bg, P);

    dim3 tg(Lc / 32, HP / 32, Bc);
    transpose_kernel<<<tg, dim3(32, 8)>>>(Qh, QhT);

    attn_tc<<<dim3(16, 8), 512, SM_ATTN>>>(Ah, P, QhT, Hm);

    out_kernel<<<BLc / 64, 256>>>(Ah, Hm, Wt, bt, out);
}

// round 14
// speedup vs baseline: 1.2905x; 1.2139x over previous
#include <cuda_runtime.h>
#include <math.h>
#include <cstdint>

#define Bc   8
#define Lc   2048
#define Dc   300
#define Hc   150
#define HP   160
#define BLc  (Bc * Lc)

__device__ float g_Qh [BLc * HP];
__device__ float g_Ah [BLc * HP];
__device__ float g_P  [BLc * HP];
__device__ float g_QhT[(size_t)Bc * HP * Lc];
__device__ float g_Hm [BLc * HP];

// ---------------- helpers (plain sm_80+ PTX, valid on compute_103) ---------
__device__ __forceinline__ uint32_t su32(const void* p) {
    return (uint32_t)__cvta_generic_to_shared(p);
}
// pack two floats to bf16x2: lower half = f0 (lower k index), upper = f1
__device__ __forceinline__ uint32_t packbf(float f0, float f1) {
    uint32_t p;
    asm("cvt.rn.bf16x2.f32 %0, %1, %2;" : "=r"(p) : "f"(f1), "f"(f0));
    return p;
}
// 2-term bf16 split of a float2 (hi + residual lo)
__device__ __forceinline__ void splitbf(float2 v, uint32_t& h, uint32_t& l) {
    h = packbf(v.x, v.y);
    float hx = __uint_as_float(h << 16);
    float hy = __uint_as_float(h & 0xffff0000u);
    l = packbf(v.x - hx, v.y - hy);
}
__device__ __forceinline__ void mma16(float* c,
    uint32_t a0, uint32_t a1, uint32_t a2, uint32_t a3, uint32_t b0, uint32_t b1)
{
    asm volatile("mma.sync.aligned.m16n8k16.row.col.f32.bf16.bf16.f32 "
        "{%0,%1,%2,%3}, {%4,%5,%6,%7}, {%8,%9}, {%0,%1,%2,%3};"
        : "+f"(c[0]), "+f"(c[1]), "+f"(c[2]), "+f"(c[3])
        : "r"(a0), "r"(a1), "r"(a2), "r"(a3), "r"(b0), "r"(b1));
}
__device__ __forceinline__ void cpa16(uint32_t s, const void* g) {
    asm volatile("cp.async.cg.shared.global [%0], [%1], 16;" :: "r"(s), "l"(g));
}
#define CP_COMMIT  asm volatile("cp.async.commit_group;" ::: "memory")
#define CP_WAIT1   asm volatile("cp.async.wait_group 1;" ::: "memory")
#define CP_WAIT0   asm volatile("cp.async.wait_group 0;" ::: "memory")

// ---------------------------------------------------------------------------
// Fused flash attention (3xBF16 m16n8k16 emulated-fp32 mma.sync).
// For each (b, a-tile of 128):
//   S = Ah_tile @ P^T (h=160), online softmax over q, O += Pexp @ Qh, Hm=O/l
// Warps 4(m=a) x 4(n). S warp n-tile 32 (q); O warp n-tile 40 (h).
// smem (floats): Ah 128x164 | R1: P-stages(2x128x36) U Pexp(128x132) |
//                R2: V-stages 2x160x36 | red 4x128 | m,l,f 3x128
// ---------------------------------------------------------------------------
#define OFF_R1  20992
#define OFF_R2  37888
#define OFF_RED 49408
#define OFF_M   49920
#define OFF_L   50048
#define OFF_F   50176
#define SM_ATTN (50304 * 4)

__global__ void __launch_bounds__(512) attn_tc(
    const float* __restrict__ Ah, const float* __restrict__ P,
    const float* __restrict__ QhT, float* __restrict__ Hm)
{
    extern __shared__ float sm[];
    float* AhS = sm;
    float* red = sm + OFF_RED;
    float* mS  = sm + OFF_M;
    float* lS  = sm + OFF_L;
    float* fS  = sm + OFF_F;

    const int tid = threadIdx.x, lane = tid & 31, wid = tid >> 5;
    const int warpM = wid & 3, warpN = wid >> 2;
    const int r4 = lane >> 2, c4 = lane & 3;
    const int b = blockIdx.y, aBase = blockIdx.x * 128;

    const float* Ab = Ah  + ((size_t)b * Lc + aBase) * HP;
    const float* Pb = P   + (size_t)b * Lc * HP;
    const float* Vb = QhT + (size_t)b * HP * Lc;

    // resident Ah tile [128][164]
    for (int i = tid; i < 128 * 40; i += 512) {
        int r = i / 40, c = (i - r * 40) * 4;
        cpa16(su32(AhS + r * 164 + c), Ab + (size_t)r * HP + c);
    }
    CP_COMMIT; CP_WAIT0;
    if (tid < 128) { mS[tid] = -1e30f; lS[tid] = 0.f; }
    __syncthreads();

    float accO[2][5][4];
    #pragma unroll
    for (int mt = 0; mt < 2; ++mt)
        #pragma unroll
        for (int nt = 0; nt < 5; ++nt)
            #pragma unroll
            for (int i = 0; i < 4; ++i) accO[mt][nt][i] = 0.f;

    const int row0b = warpM * 32 + r4;   // + mt*16 (+8)

    #pragma unroll 1
    for (int qt = 0; qt < 16; ++qt) {
        const int q0 = qt * 128;
        float accS[2][4][4];
        #pragma unroll
        for (int mt = 0; mt < 2; ++mt)
            #pragma unroll
            for (int nt = 0; nt < 4; ++nt)
                #pragma unroll
                for (int i = 0; i < 4; ++i) accS[mt][nt][i] = 0.f;

        // ---- S-GEMM over h (5 stages of 32) ----
        auto issueP = [&](int s) {
            float* d = sm + OFF_R1 + (s & 1) * (128 * 36);
            #pragma unroll 2
            for (int i = tid; i < 128 * 8; i += 512) {
                int r = i >> 3, g = i & 7;
                cpa16(su32(d + r * 36 + g * 4), Pb + (size_t)(q0 + r) * HP + s * 32 + g * 4);
            }
            CP_COMMIT;
        };
        issueP(0);
        #pragma unroll 1
        for (int s = 0; s < 5; ++s) {
            if (s + 1 < 5) { issueP(s + 1); CP_WAIT1; } else { CP_WAIT0; }
            __syncthreads();
            const float* cB = sm + OFF_R1 + (s & 1) * (128 * 36);
            const int sk = s * 32;
            #pragma unroll
            for (int kb = 0; kb < 2; ++kb) {
                const int k0 = kb * 16 + 2 * c4;
                uint32_t bH[4][2], bL[4][2];
                #pragma unroll
                for (int nt = 0; nt < 4; ++nt) {
                    int col = warpN * 32 + nt * 8 + r4;
                    splitbf(*(const float2*)&cB[col * 36 + k0],     bH[nt][0], bL[nt][0]);
                    splitbf(*(const float2*)&cB[col * 36 + k0 + 8], bH[nt][1], bL[nt][1]);
                }
                #pragma unroll
                for (int mt = 0; mt < 2; ++mt) {
                    int row = row0b + mt * 16;
                    uint32_t aH[4], aL[4];
                    splitbf(*(const float2*)&AhS[row * 164 + sk + k0],           aH[0], aL[0]);
                    splitbf(*(const float2*)&AhS[(row + 8) * 164 + sk + k0],     aH[1], aL[1]);
                    splitbf(*(const float2*)&AhS[row * 164 + sk + k0 + 8],       aH[2], aL[2]);
                    splitbf(*(const float2*)&AhS[(row + 8) * 164 + sk + k0 + 8], aH[3], aL[3]);
                    #pragma unroll
                    for (int nt = 0; nt < 4; ++nt) {
                        mma16(accS[mt][nt], aH[0], aH[1], aH[2], aH[3], bL[nt][0], bL[nt][1]);
                        mma16(accS[mt][nt], aL[0], aL[1], aL[2], aL[3], bH[nt][0], bH[nt][1]);
                        mma16(accS[mt][nt], aH[0], aH[1], aH[2], aH[3], bH[nt][0], bH[nt][1]);
                    }
                }
            }
            __syncthreads();
        }

        // ---- prefetch first V stage (overlaps softmax math) ----
        auto issueV = [&](int s) {
            float* d = sm + OFF_R2 + (s & 1) * (160 * 36);
            #pragma unroll 3
            for (int i = tid; i < 160 * 8; i += 512) {
                int r = i >> 3, g = i & 7;
                cpa16(su32(d + r * 36 + g * 4), Vb + (size_t)r * Lc + q0 + s * 32 + g * 4);
            }
            CP_COMMIT;
        };
        issueV(0);

        // ---- online softmax: tile row max ----
        #pragma unroll
        for (int mt = 0; mt < 2; ++mt) {
            int row = row0b + mt * 16;
            float m0 = -1e30f, m1 = -1e30f;
            #pragma unroll
            for (int nt = 0; nt < 4; ++nt) {
                m0 = fmaxf(m0, fmaxf(accS[mt][nt][0], accS[mt][nt][1]));
                m1 = fmaxf(m1, fmaxf(accS[mt][nt][2], accS[mt][nt][3]));
            }
            m0 = fmaxf(m0, __shfl_xor_sync(0xffffffffu, m0, 1));
            m0 = fmaxf(m0, __shfl_xor_sync(0xffffffffu, m0, 2));
            m1 = fmaxf(m1, __shfl_xor_sync(0xffffffffu, m1, 1));
            m1 = fmaxf(m1, __shfl_xor_sync(0xffffffffu, m1, 2));
            if (c4 == 0) {
                red[warpN * 128 + row]     = m0;
                red[warpN * 128 + row + 8] = m1;
            }
        }
        __syncthreads();
        if (warpN == 0 && c4 == 0) {
            #pragma unroll
            for (int mt = 0; mt < 2; ++mt)
                #pragma unroll
                for (int p = 0; p < 2; ++p) {
                    int row = row0b + mt * 16 + p * 8;
                    float t = fmaxf(fmaxf(red[row], red[128 + row]),
                                    fmaxf(red[256 + row], red[384 + row]));
                    float mo = mS[row], mn = fmaxf(mo, t);
                    fS[row] = __expf(mo - mn);
                    mS[row] = mn;
                }
        }
        __syncthreads();

        // ---- Pexp -> smem + row sums ----
        float* PE = sm + OFF_R1;   // [128][132]
        #pragma unroll
        for (int mt = 0; mt < 2; ++mt) {
            int row = row0b + mt * 16;
            float m0 = mS[row], m1 = mS[row + 8];
            float s0 = 0.f, s1 = 0.f;
            #pragma unroll
            for (int nt = 0; nt < 4; ++nt) {
                float e0 = __expf(accS[mt][nt][0] - m0);
                float e1 = __expf(accS[mt][nt][1] - m0);
                float e2 = __expf(accS[mt][nt][2] - m1);
                float e3 = __expf(accS[mt][nt][3] - m1);
                int col = warpN * 32 + nt * 8 + c4 * 2;
                *(float2*)(PE + row * 132 + col)       = make_float2(e0, e1);
                *(float2*)(PE + (row + 8) * 132 + col) = make_float2(e2, e3);
                s0 += e0 + e1; s1 += e2 + e3;
            }
            s0 += __shfl_xor_sync(0xffffffffu, s0, 1);
            s0 += __shfl_xor_sync(0xffffffffu, s0, 2);
            s1 += __shfl_xor_sync(0xffffffffu, s1, 1);
            s1 += __shfl_xor_sync(0xffffffffu, s1, 2);
            if (c4 == 0) {
                red[warpN * 128 + row]     = s0;
                red[warpN * 128 + row + 8] = s1;
            }
        }
        __syncthreads();
        if (warpN == 0 && c4 == 0) {
            #pragma unroll
            for (int mt = 0; mt < 2; ++mt)
                #pragma unroll
                for (int p = 0; p < 2; ++p) {
                    int row = row0b + mt * 16 + p * 8;
                    float ts = red[row] + red[128 + row] + red[256 + row] + red[384 + row];
                    lS[row] = lS[row] * fS[row] + ts;
                }
        }
        // ---- rescale O by factor ----
        #pragma unroll
        for (int mt = 0; mt < 2; ++mt) {
            int row = row0b + mt * 16;
            float f0 = fS[row], f1 = fS[row + 8];
            #pragma unroll
            for (int nt = 0; nt < 5; ++nt) {
                accO[mt][nt][0] *= f0; accO[mt][nt][1] *= f0;
                accO[mt][nt][2] *= f1; accO[mt][nt][3] *= f1;
            }
        }

        // ---- O-GEMM over q (4 stages of 32): O += PE @ V ----
        #pragma unroll 1
        for (int s = 0; s < 4; ++s) {
            if (s + 1 < 4) { issueV(s + 1); CP_WAIT1; } else { CP_WAIT0; }
            __syncthreads();
            const float* cB = sm + OFF_R2 + (s & 1) * (160 * 36);
            const int sq = s * 32;
            #pragma unroll
            for (int kb = 0; kb < 2; ++kb) {
                const int k0 = kb * 16 + 2 * c4;
                uint32_t bH[5][2], bL[5][2];
                #pragma unroll
                for (int nt = 0; nt < 5; ++nt) {
                    int col = warpN * 40 + nt * 8 + r4;
                    splitbf(*(const float2*)&cB[col * 36 + k0],     bH[nt][0], bL[nt][0]);
                    splitbf(*(const float2*)&cB[col * 36 + k0 + 8], bH[nt][1], bL[nt][1]);
                }
                #pragma unroll
                for (int mt = 0; mt < 2; ++mt) {
                    int row = row0b + mt * 16;
                    uint32_t aH[4], aL[4];
                    splitbf(*(const float2*)&PE[row * 132 + sq + k0],           aH[0], aL[0]);
                    splitbf(*(const float2*)&PE[(row + 8) * 132 + sq + k0],     aH[1], aL[1]);
                    splitbf(*(const float2*)&PE[row * 132 + sq + k0 + 8],       aH[2], aL[2]);
                    splitbf(*(const float2*)&PE[(row + 8) * 132 + sq + k0 + 8], aH[3], aL[3]);
                    #pragma unroll
                    for (int nt = 0; nt < 5; ++nt) {
                        mma16(accO[mt][nt], aH[0], aH[1], aH[2], aH[3], bL[nt][0], bL[nt][1]);
                        mma16(accO[mt][nt], aL[0], aL[1], aL[2], aL[3], bH[nt][0], bH[nt][1]);
                        mma16(accO[mt][nt], aH[0], aH[1], aH[2], aH[3], bH[nt][0], bH[nt][1]);
                    }
                }
            }
            __syncthreads();
        }
    }

    // ---- final: Hm = O / l ----
    #pragma unroll
    for (int mt = 0; mt < 2; ++mt) {
        int row = row0b + mt * 16;
        float i0 = 1.f / lS[row], i1 = 1.f / lS[row + 8];
        #pragma unroll
        for (int nt = 0; nt < 5; ++nt) {
            int col = warpN * 40 + nt * 8 + c4 * 2;
            size_t o0 = ((size_t)b * Lc + aBase + row) * HP + col;
            size_t o1 = ((size_t)b * Lc + aBase + row + 8) * HP + col;
            *(float2*)(Hm + o0) = make_float2(accO[mt][nt][0] * i0, accO[mt][nt][1] * i0);
            *(float2*)(Hm + o1) = make_float2(accO[mt][nt][2] * i1, accO[mt][nt][3] * i1);
        }
    }
}

// ---------------- Kernel 1: gate (FFMA, writes HP-padded) ----------------
__global__ __launch_bounds__(256) void gate_kernel(
    const float* __restrict__ X, const float* __restrict__ Wi, const float* __restrict__ Wu,
    const float* __restrict__ bi, const float* __restrict__ bu, float* __restrict__ Y)
{
    __shared__ float Xs[64 * 17], Wis[16 * 160], Wus[16 * 160];
    const int tid = threadIdx.x, tx = tid & 15, ty = tid >> 4, rb = blockIdx.x * 64;
    float accI[4][10], accU[4][10];
    #pragma unroll
    for (int i = 0; i < 4; ++i)
        #pragma unroll
        for (int j = 0; j < 10; ++j) { accI[i][j] = 0.f; accU[i][j] = 0.f; }

    for (int kk = 0; kk < Dc; kk += 16) {
        #pragma unroll
        for (int r = 0; r < 4; ++r) {
            int idx = tid + 256 * r, m = idx >> 4, k = idx & 15;
            Xs[m * 17 + k] = (kk + k < Dc) ? X[(size_t)(rb + m) * Dc + kk + k] : 0.f;
        }
        #pragma unroll
        for (int r = 0; r < 10; ++r) {
            int idx = tid + 256 * r, k = idx / 160, c = idx - k * 160;
            bool ok = (c < Hc) && (kk + k < Dc);
            Wis[k * 160 + c] = ok ? Wi[(size_t)(kk + k) * Hc + c] : 0.f;
            Wus[k * 160 + c] = ok ? Wu[(size_t)(kk + k) * Hc + c] : 0.f;
        }
        __syncthreads();
        #pragma unroll
        for (int k = 0; k < 16; ++k) {
            float xv[4];
            #pragma unroll
            for (int i = 0; i < 4; ++i) xv[i] = Xs[(ty * 4 + i) * 17 + k];
            #pragma unroll
            for (int j = 0; j < 10; ++j) {
                float wi = Wis[k * 160 + tx + 16 * j], wu = Wus[k * 160 + tx + 16 * j];
                #pragma unroll
                for (int i = 0; i < 4; ++i) { accI[i][j] += xv[i] * wi; accU[i][j] += xv[i] * wu; }
            }
        }
        __syncthreads();
    }
    #pragma unroll
    for (int j = 0; j < 10; ++j) {
        int c = tx + 16 * j;
        float bI = (c < Hc) ? bi[c] : 0.f, bU = (c < Hc) ? bu[c] : 0.f;
        #pragma unroll
        for (int i = 0; i < 4; ++i) {
            int row = rb + ty * 4 + i;
            float v = 0.f;
            if (c < Hc) {
                float si = 1.f / (1.f + expf(-(accI[i][j] + bI)));
                v = si * tanhf(accU[i][j] + bU);
            }
            Y[(size_t)row * HP + c] = v;
        }
    }
}

// ---------------- Kernel 2: P = Qh@Wg + bg ----------------
__global__ __launch_bounds__(256) void proj_kernel(
    const float* __restrict__ Xin, const float* __restrict__ Wg,
    const float* __restrict__ bg, float* __restrict__ P)
{
    __shared__ float Xs[64 * 17], Ws[16 * 160];
    const int tid = threadIdx.x, tx = tid & 15, ty = tid >> 4, rb = blockIdx.x * 64;
    float acc[4][10];
    #pragma unroll
    for (int i = 0; i < 4; ++i)
        #pragma unroll
        for (int j = 0; j < 10; ++j) acc[i][j] = 0.f;

    for (int kk = 0; kk < Hc; kk += 16) {
        #pragma unroll
        for (int r = 0; r < 4; ++r) {
            int idx = tid + 256 * r, m = idx >> 4, k = idx & 15;
            Xs[m * 17 + k] = Xin[(size_t)(rb + m) * HP + kk + k];
        }
        #pragma unroll
        for (int r = 0; r < 10; ++r) {
            int idx = tid + 256 * r, k = idx / 160, c = idx - k * 160;
            bool ok = (c < Hc) && (kk + k < Hc);
            Ws[k * 160 + c] = ok ? Wg[(size_t)(kk + k) * Hc + c] : 0.f;
        }
        __syncthreads();
        #pragma unroll
        for (int k = 0; k < 16; ++k) {
            float xv[4];
            #pragma unroll
            for (int i = 0; i < 4; ++i) xv[i] = Xs[(ty * 4 + i) * 17 + k];
            #pragma unroll
            for (int j = 0; j < 10; ++j) {
                float w = Ws[k * 160 + tx + 16 * j];
                #pragma unroll
                for (int i = 0; i < 4; ++i) acc[i][j] += xv[i] * w;
            }
        }
        __syncthreads();
    }
    #pragma unroll
    for (int j = 0; j < 10; ++j) {
        int c = tx + 16 * j;
        float bv = (c < Hc) ? bg[c] : 0.f;
        #pragma unroll
        for (int i = 0; i < 4; ++i) {
            int row = rb + ty * 4 + i;
            P[(size_t)row * HP + c] = (c < Hc) ? (acc[i][j] + bv) : 0.f;
        }
    }
}

// ---------------- Kernel 2b: QhT[b][h][q] = Qh[b][q][h] ----------------
__global__ void transpose_kernel(const float* __restrict__ Qh, float* __restrict__ QhT)
{
    __shared__ float t[32][33];
    const int tx = threadIdx.x, ty = threadIdx.y;
    const int b = blockIdx.z, q0 = blockIdx.x * 32, h0 = blockIdx.y * 32;
    #pragma unroll
    for (int j = 0; j < 4; ++j)
        t[ty + 8 * j][tx] = Qh[((size_t)b * Lc + q0 + ty + 8 * j) * HP + h0 + tx];
    __syncthreads();
    #pragma unroll
    for (int j = 0; j < 4; ++j)
        QhT[((size_t)b * HP + h0 + ty + 8 * j) * Lc + q0 + tx] = t[tx][ty + 8 * j];
}

// ---------------- Kernel 6: T = relu([Ah,Hm]@Wt + bt) ----------------
__global__ __launch_bounds__(256) void out_kernel(
    const float* __restrict__ Ah, const float* __restrict__ Hm,
    const float* __restrict__ Wt, const float* __restrict__ bt, float* __restrict__ T)
{
    __shared__ float Xs[64 * 17], Ws[16 * 160];
    const int tid = threadIdx.x, tx = tid & 15, ty = tid >> 4, rb = blockIdx.x * 64;
    float acc[4][10];
    #pragma unroll
    for (int i = 0; i < 4; ++i)
        #pragma unroll
        for (int j = 0; j < 10; ++j) acc[i][j] = 0.f;

    for (int ph = 0; ph < 2; ++ph) {
        const float* X = ph ? Hm : Ah;
        const int wofs = ph ? Hc : 0;
        for (int kk = 0; kk < Hc; kk += 16) {
            #pragma unroll
            for (int r = 0; r < 4; ++r) {
                int idx = tid + 256 * r, m = idx >> 4, k = idx & 15;
                Xs[m * 17 + k] = X[(size_t)(rb + m) * HP + kk + k];
            }
            #pragma unroll
            for (int r = 0; r < 10; ++r) {
                int idx = tid + 256 * r, k = idx / 160, c = idx - k * 160;
                bool ok = (c < Hc) && (kk + k < Hc);
                Ws[k * 160 + c] = ok ? Wt[(size_t)(wofs + kk + k) * Hc + c] : 0.f;
            }
            __syncthreads();
            #pragma unroll
            for (int k = 0; k < 16; ++k) {
                float xv[4];
                #pragma unroll
                for (int i = 0; i < 4; ++i) xv[i] = Xs[(ty * 4 + i) * 17 + k];
                #pragma unroll
                for (int j = 0; j < 10; ++j) {
                    float w = Ws[k * 160 + tx + 16 * j];
                    #pragma unroll
                    for (int i = 0; i < 4; ++i) acc[i][j] += xv[i] * w;
                }
            }
            __syncthreads();
        }
    }
    #pragma unroll
    for (int j = 0; j < 10; ++j) {
        int c = tx + 16 * j;
        if (c < Hc) {
            float bv = bt[c];
            #pragma unroll
            for (int i = 0; i < 4; ++i) {
                int row = rb + ty * 4 + i;
                T[(size_t)row * Hc + c] = fmaxf(acc[i][j] + bv, 0.f);
            }
        }
    }
}

// ---------------- Launch ----------------
extern "C" void kernel_launch(void* const* d_in, const int* in_sizes, int n_in,
                              void* d_out, int out_size)
{
    const float* Q  = (const float*)d_in[0];
    const float* A  = (const float*)d_in[1];
    const float* Wi = (const float*)d_in[2];
    const float* Wu = (const float*)d_in[3];
    const float* Wg = (const float*)d_in[4];
    const float* Wt = (const float*)d_in[5];
    const float* bi = (const float*)d_in[6];
    const float* bu = (const float*)d_in[7];
    const float* bg = (const float*)d_in[8];
    const float* bt = (const float*)d_in[9];
    float* out = (float*)d_out;

    float *Qh, *Ah, *P, *QhT, *Hm;
    cudaGetSymbolAddress((void**)&Qh,  g_Qh);
    cudaGetSymbolAddress((void**)&Ah,  g_Ah);
    cudaGetSymbolAddress((void**)&P,   g_P);
    cudaGetSymbolAddress((void**)&QhT, g_QhT);
    cudaGetSymbolAddress((void**)&Hm,  g_Hm);

    cudaFuncSetAttribute(attn_tc, cudaFuncAttributeMaxDynamicSharedMemorySize, SM_ATTN);

    gate_kernel<<<BLc / 64, 256>>>(Q, Wi, Wu, bi, bu, Qh);
    gate_kernel<<<BLc / 64, 256>>>(A, Wi, Wu, bi, bu, Ah);
    proj_kernel<<<BLc / 64, 256>>>(Qh, Wg, bg, P);

    dim3 tg(Lc / 32, HP / 32, Bc);
    transpose_kernel<<<tg, dim3(32, 8)>>>(Qh, QhT);

    attn_tc<<<dim3(16, 8), 512, SM_ATTN>>>(Ah, P, QhT, Hm);

    out_kernel<<<BLc / 64, 256>>>(Ah, Hm, Wt, bt, out);
}